// round 15
// baseline (speedup 1.0000x reference)
#include <cuda_runtime.h>
#include <cuda_fp16.h>
#include <math.h>
#include <stdint.h>

// Problem constants
#define DD   512
#define SS   512
#define BB   32
#define WW   3
#define NTOK (BB*SS)          // 16384 tokens per stream
#define NELEM ((size_t)NTOK*DD)

// ---------------------------------------------------------------------------
// Scratch (allocation-free). Row index = half*NTOK + token (half 0=fwd,1=bwd).
// Stream state lives IN the output buffer (out[l][token][half*512:]).
// ---------------------------------------------------------------------------
__device__ __half g_yh[2 * NELEM];      // window-sum residual (f16)
__device__ __half g_zh[2 * NELEM];      // layernorm output (f16)
__device__ __half g_hh[2 * NELEM];      // relu hidden (f16)
__device__ __half g_wh[12 * DD * DD];   // f16 weights, native [K,N] row-major

// ---------------------------------------------------------------------------
// Helpers
// ---------------------------------------------------------------------------
__device__ __forceinline__ uint32_t smem_u32(const void* p) {
    uint32_t a;
    asm("{ .reg .u64 t; cvta.to.shared.u64 t, %1; cvt.u32.u64 %0, t; }" : "=r"(a) : "l"(p));
    return a;
}
__device__ __forceinline__ void cp16(uint32_t s, const void* g) {
    asm volatile("cp.async.cg.shared.global [%0], [%1], 16;" :: "r"(s), "l"(g) : "memory");
}
#define CP_COMMIT() asm volatile("cp.async.commit_group;" ::: "memory")
#define CP_WAIT(N)  asm volatile("cp.async.wait_group %0;" :: "n"(N) : "memory")

__device__ __forceinline__ void ldsm_x4(uint32_t* r, uint32_t addr) {
    asm volatile("ldmatrix.sync.aligned.m8n8.x4.shared.b16 {%0,%1,%2,%3}, [%4];"
                 : "=r"(r[0]), "=r"(r[1]), "=r"(r[2]), "=r"(r[3]) : "r"(addr));
}
__device__ __forceinline__ void ldsm_x4_t(uint32_t* r, uint32_t addr) {
    asm volatile("ldmatrix.sync.aligned.m8n8.x4.trans.shared.b16 {%0,%1,%2,%3}, [%4];"
                 : "=r"(r[0]), "=r"(r[1]), "=r"(r[2]), "=r"(r[3]) : "r"(addr));
}
__device__ __forceinline__ void mma16816(float* c, const uint32_t* a, uint32_t b0, uint32_t b1) {
    asm volatile("mma.sync.aligned.m16n8k16.row.col.f32.f16.f16.f32 "
                 "{%0,%1,%2,%3}, {%4,%5,%6,%7}, {%8,%9}, {%0,%1,%2,%3};"
                 : "+f"(c[0]), "+f"(c[1]), "+f"(c[2]), "+f"(c[3])
                 : "r"(a[0]), "r"(a[1]), "r"(a[2]), "r"(a[3]), "r"(b0), "r"(b1));
}

// ---------------------------------------------------------------------------
// Prep: convert 12 weight matrices to f16 (native [K,N] layout, no transpose)
// ---------------------------------------------------------------------------
__global__ void prep_kernel(const float* __restrict__ fw1,
                            const float* __restrict__ fw2,
                            const float* __restrict__ bw1,
                            const float* __restrict__ bw2)
{
    int widx = blockIdx.y;
    int l = widx >> 2, which = widx & 3;
    const float* src = (which == 0 ? fw1 : which == 1 ? fw2 : which == 2 ? bw1 : bw2)
                       + (size_t)l * DD * DD;
    __half* dst = g_wh + (size_t)widx * DD * DD;
    int i8 = blockIdx.x * 256 + threadIdx.x;
    float4 v1 = *(const float4*)(src + (size_t)i8 * 8);
    float4 v2 = *(const float4*)(src + (size_t)i8 * 8 + 4);
    __half2 h0 = __floats2half2_rn(v1.x, v1.y);
    __half2 h1 = __floats2half2_rn(v1.z, v1.w);
    __half2 h2 = __floats2half2_rn(v2.x, v2.y);
    __half2 h3 = __floats2half2_rn(v2.z, v2.w);
    uint4 o;
    o.x = *reinterpret_cast<unsigned*>(&h0);
    o.y = *reinterpret_cast<unsigned*>(&h1);
    o.z = *reinterpret_cast<unsigned*>(&h2);
    o.w = *reinterpret_cast<unsigned*>(&h3);
    *reinterpret_cast<uint4*>(dst + (size_t)i8 * 8) = o;
}

// ---------------------------------------------------------------------------
// Kernel 1: fused window-sum + LayerNorm, BOTH streams in one launch.
// ---------------------------------------------------------------------------
__global__ void winln_kernel(const float* __restrict__ x0,
                             const float* __restrict__ prev,   // out slice base (layer-1)
                             const float* __restrict__ padf,
                             const float* __restrict__ padb,
                             const float* __restrict__ wvf,
                             const float* __restrict__ wvb,
                             const float* __restrict__ gf,
                             const float* __restrict__ bef,
                             const float* __restrict__ gb,
                             const float* __restrict__ beb,
                             int use_x0)
{
    int gtok  = blockIdx.x;
    int half  = gtok >> 14;              // 0 fwd, 1 bwd
    int token = gtok & (NTOK - 1);
    int b = token >> 9;
    int t = token & (SS - 1);
    int tid = threadIdx.x;
    int d = tid * 4;

    const float* __restrict__ xin;
    int xstride;
    if (use_x0) { xin = x0;                          xstride = DD;   }
    else        { xin = prev + (half ? 512 : 0);     xstride = 1024; }

    const float* __restrict__ wv    = half ? wvb : wvf;
    const float* __restrict__ gamma = half ? gb  : gf;
    const float* __restrict__ beta  = half ? beb : bef;
    int offset = half ? WW : 0;

    float wk[4] = {wv[0], wv[1], wv[2], wv[3]};
    int j0 = t + offset;

    float4 acc = make_float4(0.f, 0.f, 0.f, 0.f);
    if (j0 >= WW && j0 + 3 < WW + SS) {
        const float* p = xin + (size_t)(b * SS + (j0 - WW)) * xstride + d;
#pragma unroll
        for (int k = 0; k < 4; k++) {
            float4 v = *(const float4*)(p + (size_t)k * xstride);
            acc.x = fmaf(wk[k], v.x, acc.x);
            acc.y = fmaf(wk[k], v.y, acc.y);
            acc.z = fmaf(wk[k], v.z, acc.z);
            acc.w = fmaf(wk[k], v.w, acc.w);
        }
    } else {
#pragma unroll
        for (int k = 0; k < 4; k++) {
            int j = j0 + k;
            float4 v;
            if (j < WW)           v = *(const float4*)(padf + (size_t)j * DD + d);
            else if (j < WW + SS) v = *(const float4*)(xin + (size_t)(b * SS + (j - WW)) * xstride + d);
            else                  v = *(const float4*)(padb + (size_t)(j - WW - SS) * DD + d);
            acc.x = fmaf(wk[k], v.x, acc.x);
            acc.y = fmaf(wk[k], v.y, acc.y);
            acc.z = fmaf(wk[k], v.z, acc.z);
            acc.w = fmaf(wk[k], v.w, acc.w);
        }
    }

    float sum = acc.x + acc.y + acc.z + acc.w;
    float sq  = acc.x * acc.x + acc.y * acc.y + acc.z * acc.z + acc.w * acc.w;
#pragma unroll
    for (int o = 16; o > 0; o >>= 1) {
        sum += __shfl_down_sync(0xffffffffu, sum, o);
        sq  += __shfl_down_sync(0xffffffffu, sq , o);
    }
    __shared__ float s1[4], s2[4];
    int wid = tid >> 5, lane = tid & 31;
    if (lane == 0) { s1[wid] = sum; s2[wid] = sq; }
    __syncthreads();
    float tot  = s1[0] + s1[1] + s1[2] + s1[3];
    float tot2 = s2[0] + s2[1] + s2[2] + s2[3];

    float mean = tot * (1.0f / DD);
    float var  = (tot2 - tot * mean) * (1.0f / (DD - 1));
    var = fmaxf(var, 0.f);
    float inv = 1.0f / (sqrtf(var) + 1e-6f);

    size_t idx = (size_t)gtok * DD + d;
    float4 gm = *(const float4*)(gamma + d);
    float4 bt = *(const float4*)(beta + d);
    float zx = fmaf(gm.x, (acc.x - mean) * inv, bt.x);
    float zy = fmaf(gm.y, (acc.y - mean) * inv, bt.y);
    float zz = fmaf(gm.z, (acc.z - mean) * inv, bt.z);
    float zw = fmaf(gm.w, (acc.w - mean) * inv, bt.w);

    __half2 y0 = __floats2half2_rn(acc.x, acc.y);
    __half2 y1 = __floats2half2_rn(acc.z, acc.w);
    uint2 yo;
    yo.x = *reinterpret_cast<unsigned*>(&y0);
    yo.y = *reinterpret_cast<unsigned*>(&y1);
    *reinterpret_cast<uint2*>(g_yh + idx) = yo;

    __half2 z0 = __floats2half2_rn(zx, zy);
    __half2 z1 = __floats2half2_rn(zz, zw);
    uint2 zo;
    zo.x = *reinterpret_cast<unsigned*>(&z0);
    zo.y = *reinterpret_cast<unsigned*>(&z1);
    *reinterpret_cast<uint2*>(g_zh + idx) = zo;
}

// ---------------------------------------------------------------------------
// Kernel 2: fp16 mma GEMM  [32768 x 512] @ W[512(k) x 512(n)], fp32 accum.
//   CTA 128x128, BK=64, 3-stage cp.async (wait_group 1), ldmatrix + raw mma.
//   2 CTAs/SM (3 x 35 KB = 105 KB/CTA). Direct fragment-layout epilogue.
//   MODE 0: h = f16(relu(z @ W1 + b1))
//   MODE 1: out = y + h @ W2 + b2   (sole store — out doubles as next state)
// ---------------------------------------------------------------------------
#define BM 128
#define BN 128
#define BK 64
#define AHB 144                             // A smem row stride bytes (128B + pad)
#define BHB 272                             // B smem row stride bytes (256B + pad)
#define A_BYTES (BM * AHB)                  // 18432
#define B_BYTES (BK * BHB)                  // 17408
#define STAGE_BYTES (A_BYTES + B_BYTES)     // 35840
#define SMEM_BYTES (3 * STAGE_BYTES)        // 107520 (x2 CTA = 210 KB < 228 KB)
#define NCH (DD / BK)                       // 8
#define KSTEPS (BK / 16)                    // 4 k16-steps per chunk

template<int MODE>
__global__ void __launch_bounds__(256, 2)
gemm_kernel(int widx_f, int widx_b,
            const float* __restrict__ bias_f,
            const float* __restrict__ bias_b,
            float* __restrict__ outp,
            long long outbase)
{
    extern __shared__ __align__(16) char smem[];

    int tid = threadIdx.x;
    int lane = tid & 31;
    int n0 = blockIdx.x * BN;
    int m0 = blockIdx.y * BM;              // global row over 32768
    int half_m = blockIdx.y >> 7;          // 0 fwd, 1 bwd

    const __half* __restrict__ A  = (MODE == 0) ? g_zh : g_hh;
    const __half* __restrict__ Wm = g_wh + (size_t)(half_m ? widx_b : widx_f) * DD * DD;
    const float* __restrict__ bias = half_m ? bias_b : bias_f;

    int warp = tid >> 5;
    int warp_m = warp >> 1;      // rows warp_m*32
    int warp_n = warp & 1;       // cols warp_n*64

    uint32_t sbase = smem_u32(smem);

    // staging: 4 cp16/thread each for A and B per chunk
    // A: 128 rows x 8 16B-groups (64 f16/row); B: 64 rows x 16 16B-groups
    int arow[4], ac8[4], brow[4], bc8[4];
#pragma unroll
    for (int i = 0; i < 4; i++) {
        int idx = tid + i * 256;
        arow[i] = idx >> 3;  ac8[i] = idx & 7;
        brow[i] = idx >> 4;  bc8[i] = idx & 15;
    }

    // ldmatrix per-lane address components
    int a_r   = (lane & 7) + ((lane >> 3) & 1) * 8;
    int a_c16 = (lane >> 4) & 1;
    int b_kr  = ((lane >> 3) & 1) * 8 + (lane & 7);
    int b_nb  = ((lane >> 4) & 1) * 8;

    float acc[2][8][4];
#pragma unroll
    for (int i = 0; i < 2; i++)
#pragma unroll
        for (int j = 0; j < 8; j++)
#pragma unroll
            for (int v = 0; v < 4; v++) acc[i][j][v] = 0.f;

    // prologue: prefetch chunks 0 and 1
#pragma unroll
    for (int c = 0; c < 2; c++) {
        int k0 = c * BK;
        uint32_t sa = sbase + c * STAGE_BYTES;
        uint32_t sb = sa + A_BYTES;
#pragma unroll
        for (int i = 0; i < 4; i++) {
            cp16(sa + arow[i] * AHB + ac8[i] * 16,
                 A + (size_t)(m0 + arow[i]) * DD + k0 + ac8[i] * 8);
            cp16(sb + brow[i] * BHB + bc8[i] * 16,
                 Wm + (size_t)(k0 + brow[i]) * DD + n0 + bc8[i] * 8);
        }
        CP_COMMIT();
    }

    for (int c = 0; c < NCH; c++) {
        if (c < NCH - 1) { CP_WAIT(1); } else { CP_WAIT(0); }
        __syncthreads();

        // prefetch chunk c+2 (its buffer finished compute last iteration)
        if (c + 2 < NCH) {
            int st = (c + 2) % 3;
            int k0 = (c + 2) * BK;
            uint32_t sa = sbase + st * STAGE_BYTES;
            uint32_t sb = sa + A_BYTES;
#pragma unroll
            for (int i = 0; i < 4; i++) {
                cp16(sa + arow[i] * AHB + ac8[i] * 16,
                     A + (size_t)(m0 + arow[i]) * DD + k0 + ac8[i] * 8);
                cp16(sb + brow[i] * BHB + bc8[i] * 16,
                     Wm + (size_t)(k0 + brow[i]) * DD + n0 + bc8[i] * 8);
            }
            CP_COMMIT();
        }

        uint32_t Ab = sbase + (c % 3) * STAGE_BYTES;
        uint32_t Bb = Ab + A_BYTES;

#pragma unroll
        for (int ks = 0; ks < KSTEPS; ks++) {       // four k16 steps per chunk
            uint32_t af[2][4];
#pragma unroll
            for (int i = 0; i < 2; i++)
                ldsm_x4(af[i], Ab + (warp_m * 32 + i * 16 + a_r) * AHB
                               + ks * 32 + a_c16 * 16);
            uint32_t bf[4][4];
#pragma unroll
            for (int jj = 0; jj < 4; jj++)
                ldsm_x4_t(bf[jj], Bb + (ks * 16 + b_kr) * BHB
                                 + (warp_n * 64 + jj * 16 + b_nb) * 2);
#pragma unroll
            for (int i = 0; i < 2; i++)
#pragma unroll
                for (int j = 0; j < 8; j++) {
                    int jj = j >> 1, sel = (j & 1) * 2;
                    mma16816(acc[i][j], af[i], bf[jj][sel], bf[jj][sel + 1]);
                }
        }
    }

    // --------------------------------------------------------------
    // Direct epilogue from fragment layout (no smem staging, no sync)
    // --------------------------------------------------------------
    int g = lane >> 2, tq = lane & 3;
#pragma unroll
    for (int i = 0; i < 2; i++) {
        int r0 = m0 + warp_m * 32 + i * 16 + g;       // global row
#pragma unroll
        for (int j = 0; j < 8; j++) {
            int col = n0 + warp_n * 64 + j * 8 + tq * 2;
            float2 bs = *(const float2*)(bias + col);
            float o0 = acc[i][j][0] + bs.x;
            float o1 = acc[i][j][1] + bs.y;
            float o2 = acc[i][j][2] + bs.x;
            float o3 = acc[i][j][3] + bs.y;
            if (MODE == 0) {
                __half2 h0 = __floats2half2_rn(fmaxf(o0, 0.f), fmaxf(o1, 0.f));
                __half2 h1 = __floats2half2_rn(fmaxf(o2, 0.f), fmaxf(o3, 0.f));
                *reinterpret_cast<unsigned*>(g_hh + (size_t)r0 * DD + col) =
                    *reinterpret_cast<unsigned*>(&h0);
                *reinterpret_cast<unsigned*>(g_hh + (size_t)(r0 + 8) * DD + col) =
                    *reinterpret_cast<unsigned*>(&h1);
            } else {
                __half2 yh0 = *reinterpret_cast<const __half2*>(g_yh + (size_t)r0 * DD + col);
                __half2 yh1 = *reinterpret_cast<const __half2*>(g_yh + (size_t)(r0 + 8) * DD + col);
                float2 y0 = __half22float2(yh0);
                float2 y1 = __half22float2(yh1);
                o0 += y0.x; o1 += y0.y; o2 += y1.x; o3 += y1.y;
                int ocol = (half_m ? 512 : 0) + col;
                size_t ob = (size_t)outbase;
                *(float2*)(outp + ob + (size_t)(r0 & (NTOK - 1)) * 1024 + ocol)
                    = make_float2(o0, o1);
                *(float2*)(outp + ob + (size_t)((r0 + 8) & (NTOK - 1)) * 1024 + ocol)
                    = make_float2(o2, o3);
            }
        }
    }
}

// ---------------------------------------------------------------------------
// Launch: prep + 3 layers x (winln, gemm1, gemm2)  (fwd+bwd merged)
// ---------------------------------------------------------------------------
extern "C" void kernel_launch(void* const* d_in, const int* in_sizes, int n_in,
                              void* d_out, int out_size)
{
    const float* x       = (const float*)d_in[0];
    const float* fwd_pad = (const float*)d_in[1];
    const float* bwd_pad = (const float*)d_in[2];
    const float* fwd_w   = (const float*)d_in[3];
    const float* bwd_w   = (const float*)d_in[4];
    const float* fwd_w1  = (const float*)d_in[5];
    const float* fwd_b1  = (const float*)d_in[6];
    const float* fwd_w2  = (const float*)d_in[7];
    const float* fwd_b2  = (const float*)d_in[8];
    const float* fwd_g   = (const float*)d_in[9];
    const float* fwd_be  = (const float*)d_in[10];
    const float* bwd_w1  = (const float*)d_in[11];
    const float* bwd_b1  = (const float*)d_in[12];
    const float* bwd_w2  = (const float*)d_in[13];
    const float* bwd_b2  = (const float*)d_in[14];
    const float* bwd_g   = (const float*)d_in[15];
    const float* bwd_be  = (const float*)d_in[16];
    float* out = (float*)d_out;

    static int smem_set = 0;
    if (!smem_set) {
        cudaFuncSetAttribute(gemm_kernel<0>, cudaFuncAttributeMaxDynamicSharedMemorySize, SMEM_BYTES);
        cudaFuncSetAttribute(gemm_kernel<1>, cudaFuncAttributeMaxDynamicSharedMemorySize, SMEM_BYTES);
        smem_set = 1;
    }

    prep_kernel<<<dim3(128, 12), 256>>>(fwd_w1, fwd_w2, bwd_w1, bwd_w2);

    dim3 ggrid(4, 256);   // N tiles x M tiles (both halves)

    for (int l = 0; l < 3; l++) {
        const float* pf = fwd_pad + (size_t)l * WW * DD;
        const float* pb = bwd_pad + (size_t)l * WW * DD;
        long long obase = (long long)l * NTOK * 1024;
        int use_x0 = (l == 0) ? 1 : 0;
        const float* prev = out + (size_t)(l > 0 ? (l - 1) : 0) * NTOK * 1024;

        winln_kernel<<<2 * NTOK, 128>>>(x, prev, pf, pb,
                                        fwd_w + l * (WW + 1), bwd_w + l * (WW + 1),
                                        fwd_g + l * DD, fwd_be + l * DD,
                                        bwd_g + l * DD, bwd_be + l * DD,
                                        use_x0);
        gemm_kernel<0><<<ggrid, 256, SMEM_BYTES>>>(l * 4 + 0, l * 4 + 2,
                                                   fwd_b1 + l * DD, bwd_b1 + l * DD,
                                                   nullptr, 0);
        gemm_kernel<1><<<ggrid, 256, SMEM_BYTES>>>(l * 4 + 1, l * 4 + 3,
                                                   fwd_b2 + l * DD, bwd_b2 + l * DD,
                                                   out, obase);
    }
}

// round 16
// speedup vs baseline: 1.7147x; 1.7147x over previous
#include <cuda_runtime.h>
#include <cuda_fp16.h>
#include <math.h>
#include <stdint.h>

// Problem constants
#define DD   512
#define SS   512
#define BB   32
#define WW   3
#define NTOK (BB*SS)          // 16384 tokens per stream
#define NELEM ((size_t)NTOK*DD)

// ---------------------------------------------------------------------------
// Scratch (allocation-free). Row index = half*NTOK + token (half 0=fwd,1=bwd).
// Stream state lives IN the output buffer (out[l][token][half*512:]).
// ---------------------------------------------------------------------------
__device__ __half g_yh[2 * NELEM];      // window-sum residual (f16)
__device__ __half g_zh[2 * NELEM];      // layernorm output (f16)
__device__ __half g_hh[2 * NELEM];      // relu hidden (f16)
__device__ __half g_wh[12 * DD * DD];   // f16 weights, native [K,N] row-major

// ---------------------------------------------------------------------------
// Helpers
// ---------------------------------------------------------------------------
__device__ __forceinline__ uint32_t smem_u32(const void* p) {
    uint32_t a;
    asm("{ .reg .u64 t; cvta.to.shared.u64 t, %1; cvt.u32.u64 %0, t; }" : "=r"(a) : "l"(p));
    return a;
}
__device__ __forceinline__ void cp16(uint32_t s, const void* g) {
    asm volatile("cp.async.cg.shared.global [%0], [%1], 16;" :: "r"(s), "l"(g) : "memory");
}
#define CP_COMMIT() asm volatile("cp.async.commit_group;" ::: "memory")
#define CP_WAIT(N)  asm volatile("cp.async.wait_group %0;" :: "n"(N) : "memory")

__device__ __forceinline__ void ldsm_x4(uint32_t* r, uint32_t addr) {
    asm volatile("ldmatrix.sync.aligned.m8n8.x4.shared.b16 {%0,%1,%2,%3}, [%4];"
                 : "=r"(r[0]), "=r"(r[1]), "=r"(r[2]), "=r"(r[3]) : "r"(addr));
}
__device__ __forceinline__ void ldsm_x4_t(uint32_t* r, uint32_t addr) {
    asm volatile("ldmatrix.sync.aligned.m8n8.x4.trans.shared.b16 {%0,%1,%2,%3}, [%4];"
                 : "=r"(r[0]), "=r"(r[1]), "=r"(r[2]), "=r"(r[3]) : "r"(addr));
}
__device__ __forceinline__ void mma16816(float* c, const uint32_t* a, uint32_t b0, uint32_t b1) {
    asm volatile("mma.sync.aligned.m16n8k16.row.col.f32.f16.f16.f32 "
                 "{%0,%1,%2,%3}, {%4,%5,%6,%7}, {%8,%9}, {%0,%1,%2,%3};"
                 : "+f"(c[0]), "+f"(c[1]), "+f"(c[2]), "+f"(c[3])
                 : "r"(a[0]), "r"(a[1]), "r"(a[2]), "r"(a[3]), "r"(b0), "r"(b1));
}

// ---------------------------------------------------------------------------
// Prep: convert 12 weight matrices to f16 (native [K,N] layout, no transpose)
// ---------------------------------------------------------------------------
__global__ void prep_kernel(const float* __restrict__ fw1,
                            const float* __restrict__ fw2,
                            const float* __restrict__ bw1,
                            const float* __restrict__ bw2)
{
    int widx = blockIdx.y;
    int l = widx >> 2, which = widx & 3;
    const float* src = (which == 0 ? fw1 : which == 1 ? fw2 : which == 2 ? bw1 : bw2)
                       + (size_t)l * DD * DD;
    __half* dst = g_wh + (size_t)widx * DD * DD;
    int i8 = blockIdx.x * 256 + threadIdx.x;
    float4 v1 = *(const float4*)(src + (size_t)i8 * 8);
    float4 v2 = *(const float4*)(src + (size_t)i8 * 8 + 4);
    __half2 h0 = __floats2half2_rn(v1.x, v1.y);
    __half2 h1 = __floats2half2_rn(v1.z, v1.w);
    __half2 h2 = __floats2half2_rn(v2.x, v2.y);
    __half2 h3 = __floats2half2_rn(v2.z, v2.w);
    uint4 o;
    o.x = *reinterpret_cast<unsigned*>(&h0);
    o.y = *reinterpret_cast<unsigned*>(&h1);
    o.z = *reinterpret_cast<unsigned*>(&h2);
    o.w = *reinterpret_cast<unsigned*>(&h3);
    *reinterpret_cast<uint4*>(dst + (size_t)i8 * 8) = o;
}

// ---------------------------------------------------------------------------
// Kernel 1: fused window-sum + LayerNorm. WARP-PER-TOKEN, no smem, no barrier.
// 256 threads = 8 warps = 8 tokens per block; lane owns 16 channels (4 float4).
// xin = x (layer 0, stride 512) or prev out slice (stride 1024).
// ---------------------------------------------------------------------------
__global__ void __launch_bounds__(256)
winln_kernel(const float* __restrict__ x0,
             const float* __restrict__ prev,
             const float* __restrict__ padf,
             const float* __restrict__ padb,
             const float* __restrict__ wvf,
             const float* __restrict__ wvb,
             const float* __restrict__ gf,
             const float* __restrict__ bef,
             const float* __restrict__ gb,
             const float* __restrict__ beb,
             int use_x0)
{
    int warp = threadIdx.x >> 5;
    int lane = threadIdx.x & 31;
    int gtok = blockIdx.x * 8 + warp;
    int half = gtok >> 14;               // 0 fwd, 1 bwd
    int token = gtok & (NTOK - 1);
    int b = token >> 9;
    int t = token & (SS - 1);

    const float* __restrict__ xin;
    int xstride;
    if (use_x0) { xin = x0;                      xstride = DD;   }
    else        { xin = prev + (half ? 512 : 0); xstride = 1024; }

    const float* __restrict__ wv    = half ? wvb : wvf;
    const float* __restrict__ gamma = half ? gb  : gf;
    const float* __restrict__ beta  = half ? beb : bef;
    int offset = half ? WW : 0;

    float wk[4] = {wv[0], wv[1], wv[2], wv[3]};
    int j0 = t + offset;

    // lane channels: float4 groups at d = (lane + i*32)*4, i = 0..3
    float4 acc[4];
#pragma unroll
    for (int i = 0; i < 4; i++) acc[i] = make_float4(0.f, 0.f, 0.f, 0.f);

    if (j0 >= WW && j0 + 3 < WW + SS) {
        const float* p = xin + (size_t)(b * SS + (j0 - WW)) * xstride;
#pragma unroll
        for (int k = 0; k < 4; k++) {
            const float* pr = p + (size_t)k * xstride;
#pragma unroll
            for (int i = 0; i < 4; i++) {
                int d = (lane + i * 32) * 4;
                float4 v = *(const float4*)(pr + d);
                acc[i].x = fmaf(wk[k], v.x, acc[i].x);
                acc[i].y = fmaf(wk[k], v.y, acc[i].y);
                acc[i].z = fmaf(wk[k], v.z, acc[i].z);
                acc[i].w = fmaf(wk[k], v.w, acc[i].w);
            }
        }
    } else {
#pragma unroll
        for (int k = 0; k < 4; k++) {
            int j = j0 + k;
            const float* pr;
            int str;
            if (j < WW)           { pr = padf + (size_t)j * DD;                      str = 1; }
            else if (j < WW + SS) { pr = xin + (size_t)(b * SS + (j - WW)) * xstride; str = 1; }
            else                  { pr = padb + (size_t)(j - WW - SS) * DD;           str = 1; }
            (void)str;
#pragma unroll
            for (int i = 0; i < 4; i++) {
                int d = (lane + i * 32) * 4;
                float4 v = *(const float4*)(pr + d);
                acc[i].x = fmaf(wk[k], v.x, acc[i].x);
                acc[i].y = fmaf(wk[k], v.y, acc[i].y);
                acc[i].z = fmaf(wk[k], v.z, acc[i].z);
                acc[i].w = fmaf(wk[k], v.w, acc[i].w);
            }
        }
    }

    float sum = 0.f, sq = 0.f;
#pragma unroll
    for (int i = 0; i < 4; i++) {
        sum += acc[i].x + acc[i].y + acc[i].z + acc[i].w;
        sq = fmaf(acc[i].x, acc[i].x, sq);
        sq = fmaf(acc[i].y, acc[i].y, sq);
        sq = fmaf(acc[i].z, acc[i].z, sq);
        sq = fmaf(acc[i].w, acc[i].w, sq);
    }
    // butterfly: all lanes end with full sums
#pragma unroll
    for (int o = 16; o > 0; o >>= 1) {
        sum += __shfl_xor_sync(0xffffffffu, sum, o);
        sq  += __shfl_xor_sync(0xffffffffu, sq , o);
    }

    float mean = sum * (1.0f / DD);
    float var  = (sq - sum * mean) * (1.0f / (DD - 1));
    var = fmaxf(var, 0.f);
    float inv = 1.0f / (sqrtf(var) + 1e-6f);

    size_t base = (size_t)gtok * DD;
#pragma unroll
    for (int i = 0; i < 4; i++) {
        int d = (lane + i * 32) * 4;
        float4 gm = *(const float4*)(gamma + d);
        float4 bt = *(const float4*)(beta + d);
        float zx = fmaf(gm.x, (acc[i].x - mean) * inv, bt.x);
        float zy = fmaf(gm.y, (acc[i].y - mean) * inv, bt.y);
        float zz = fmaf(gm.z, (acc[i].z - mean) * inv, bt.z);
        float zw = fmaf(gm.w, (acc[i].w - mean) * inv, bt.w);

        __half2 y0 = __floats2half2_rn(acc[i].x, acc[i].y);
        __half2 y1 = __floats2half2_rn(acc[i].z, acc[i].w);
        uint2 yo;
        yo.x = *reinterpret_cast<unsigned*>(&y0);
        yo.y = *reinterpret_cast<unsigned*>(&y1);
        *reinterpret_cast<uint2*>(g_yh + base + d) = yo;

        __half2 z0 = __floats2half2_rn(zx, zy);
        __half2 z1 = __floats2half2_rn(zz, zw);
        uint2 zo;
        zo.x = *reinterpret_cast<unsigned*>(&z0);
        zo.y = *reinterpret_cast<unsigned*>(&z1);
        *reinterpret_cast<uint2*>(g_zh + base + d) = zo;
    }
}

// ---------------------------------------------------------------------------
// Kernel 2: fp16 mma GEMM  [32768 x 512] @ W[512(k) x 512(n)], fp32 accum.
//   EXACT R12 configuration: CTA 128x128, BK=32, 3-stage cp.async
//   (wait_group 1), ldmatrix + raw mma, direct fragment-layout epilogue.
//   MODE 0: h = f16(relu(z @ W1 + b1))
//   MODE 1: out = y + h @ W2 + b2   (sole store — out doubles as next state)
// ---------------------------------------------------------------------------
#define BM 128
#define BN 128
#define BK 32
#define AHB 80                              // A smem row stride bytes
#define BHB 272                             // B smem row stride bytes
#define A_BYTES (BM * AHB)                  // 10240
#define B_BYTES (BK * BHB)                  // 8704
#define STAGE_BYTES (A_BYTES + B_BYTES)     // 18944
#define SMEM_BYTES (3 * STAGE_BYTES)        // 56832
#define NCH (DD / BK)                       // 16

template<int MODE>
__global__ void __launch_bounds__(256, 2)
gemm_kernel(int widx_f, int widx_b,
            const float* __restrict__ bias_f,
            const float* __restrict__ bias_b,
            float* __restrict__ outp,
            long long outbase)
{
    extern __shared__ __align__(16) char smem[];

    int tid = threadIdx.x;
    int lane = tid & 31;
    int n0 = blockIdx.x * BN;
    int m0 = blockIdx.y * BM;              // global row over 32768
    int half_m = blockIdx.y >> 7;          // 0 fwd, 1 bwd

    const __half* __restrict__ A  = (MODE == 0) ? g_zh : g_hh;
    const __half* __restrict__ Wm = g_wh + (size_t)(half_m ? widx_b : widx_f) * DD * DD;
    const float* __restrict__ bias = half_m ? bias_b : bias_f;

    int warp = tid >> 5;
    int warp_m = warp >> 1;      // rows warp_m*32
    int warp_n = warp & 1;       // cols warp_n*64

    uint32_t sbase = smem_u32(smem);

    // staging: 2 cp16/thread each for A and B per chunk
    int arow[2], ac8[2], brow[2], bc8[2];
#pragma unroll
    for (int i = 0; i < 2; i++) {
        int idx = tid + i * 256;
        arow[i] = idx >> 2;  ac8[i] = idx & 3;
        brow[i] = idx >> 4;  bc8[i] = idx & 15;
    }

    // ldmatrix per-lane address components
    int a_r   = (lane & 7) + ((lane >> 3) & 1) * 8;
    int a_c16 = (lane >> 4) & 1;
    int b_kr  = ((lane >> 3) & 1) * 8 + (lane & 7);
    int b_nb  = ((lane >> 4) & 1) * 8;

    float acc[2][8][4];
#pragma unroll
    for (int i = 0; i < 2; i++)
#pragma unroll
        for (int j = 0; j < 8; j++)
#pragma unroll
            for (int v = 0; v < 4; v++) acc[i][j][v] = 0.f;

    // prologue: prefetch chunks 0 and 1
#pragma unroll
    for (int c = 0; c < 2; c++) {
        int k0 = c * BK;
        uint32_t sa = sbase + c * STAGE_BYTES;
        uint32_t sb = sa + A_BYTES;
#pragma unroll
        for (int i = 0; i < 2; i++) {
            cp16(sa + arow[i] * AHB + ac8[i] * 16,
                 A + (size_t)(m0 + arow[i]) * DD + k0 + ac8[i] * 8);
            cp16(sb + brow[i] * BHB + bc8[i] * 16,
                 Wm + (size_t)(k0 + brow[i]) * DD + n0 + bc8[i] * 8);
        }
        CP_COMMIT();
    }

    for (int c = 0; c < NCH; c++) {
        if (c < NCH - 1) { CP_WAIT(1); } else { CP_WAIT(0); }
        __syncthreads();

        // prefetch chunk c+2 (its buffer finished compute last iteration)
        if (c + 2 < NCH) {
            int st = (c + 2) % 3;
            int k0 = (c + 2) * BK;
            uint32_t sa = sbase + st * STAGE_BYTES;
            uint32_t sb = sa + A_BYTES;
#pragma unroll
            for (int i = 0; i < 2; i++) {
                cp16(sa + arow[i] * AHB + ac8[i] * 16,
                     A + (size_t)(m0 + arow[i]) * DD + k0 + ac8[i] * 8);
                cp16(sb + brow[i] * BHB + bc8[i] * 16,
                     Wm + (size_t)(k0 + brow[i]) * DD + n0 + bc8[i] * 8);
            }
            CP_COMMIT();
        }

        uint32_t Ab = sbase + (c % 3) * STAGE_BYTES;
        uint32_t Bb = Ab + A_BYTES;

#pragma unroll
        for (int ks = 0; ks < 2; ks++) {            // two k16 steps per chunk
            uint32_t af[2][4];
#pragma unroll
            for (int i = 0; i < 2; i++)
                ldsm_x4(af[i], Ab + (warp_m * 32 + i * 16 + a_r) * AHB
                               + ks * 32 + a_c16 * 16);
            uint32_t bf[4][4];
#pragma unroll
            for (int jj = 0; jj < 4; jj++)
                ldsm_x4_t(bf[jj], Bb + (ks * 16 + b_kr) * BHB
                                 + (warp_n * 64 + jj * 16 + b_nb) * 2);
#pragma unroll
            for (int i = 0; i < 2; i++)
#pragma unroll
                for (int j = 0; j < 8; j++) {
                    int jj = j >> 1, sel = (j & 1) * 2;
                    mma16816(acc[i][j], af[i], bf[jj][sel], bf[jj][sel + 1]);
                }
        }
    }

    // --------------------------------------------------------------
    // Direct epilogue from fragment layout (no smem staging, no sync)
    // --------------------------------------------------------------
    int g = lane >> 2, tq = lane & 3;
#pragma unroll
    for (int i = 0; i < 2; i++) {
        int r0 = m0 + warp_m * 32 + i * 16 + g;       // global row
#pragma unroll
        for (int j = 0; j < 8; j++) {
            int col = n0 + warp_n * 64 + j * 8 + tq * 2;
            float2 bs = *(const float2*)(bias + col);
            float o0 = acc[i][j][0] + bs.x;
            float o1 = acc[i][j][1] + bs.y;
            float o2 = acc[i][j][2] + bs.x;
            float o3 = acc[i][j][3] + bs.y;
            if (MODE == 0) {
                __half2 h0 = __floats2half2_rn(fmaxf(o0, 0.f), fmaxf(o1, 0.f));
                __half2 h1 = __floats2half2_rn(fmaxf(o2, 0.f), fmaxf(o3, 0.f));
                *reinterpret_cast<unsigned*>(g_hh + (size_t)r0 * DD + col) =
                    *reinterpret_cast<unsigned*>(&h0);
                *reinterpret_cast<unsigned*>(g_hh + (size_t)(r0 + 8) * DD + col) =
                    *reinterpret_cast<unsigned*>(&h1);
            } else {
                __half2 yh0 = *reinterpret_cast<const __half2*>(g_yh + (size_t)r0 * DD + col);
                __half2 yh1 = *reinterpret_cast<const __half2*>(g_yh + (size_t)(r0 + 8) * DD + col);
                float2 y0 = __half22float2(yh0);
                float2 y1 = __half22float2(yh1);
                o0 += y0.x; o1 += y0.y; o2 += y1.x; o3 += y1.y;
                int ocol = (half_m ? 512 : 0) + col;
                size_t ob = (size_t)outbase;
                *(float2*)(outp + ob + (size_t)(r0 & (NTOK - 1)) * 1024 + ocol)
                    = make_float2(o0, o1);
                *(float2*)(outp + ob + (size_t)((r0 + 8) & (NTOK - 1)) * 1024 + ocol)
                    = make_float2(o2, o3);
            }
        }
    }
}

// ---------------------------------------------------------------------------
// Launch: prep + 3 layers x (winln, gemm1, gemm2)  (fwd+bwd merged)
// ---------------------------------------------------------------------------
extern "C" void kernel_launch(void* const* d_in, const int* in_sizes, int n_in,
                              void* d_out, int out_size)
{
    const float* x       = (const float*)d_in[0];
    const float* fwd_pad = (const float*)d_in[1];
    const float* bwd_pad = (const float*)d_in[2];
    const float* fwd_w   = (const float*)d_in[3];
    const float* bwd_w   = (const float*)d_in[4];
    const float* fwd_w1  = (const float*)d_in[5];
    const float* fwd_b1  = (const float*)d_in[6];
    const float* fwd_w2  = (const float*)d_in[7];
    const float* fwd_b2  = (const float*)d_in[8];
    const float* fwd_g   = (const float*)d_in[9];
    const float* fwd_be  = (const float*)d_in[10];
    const float* bwd_w1  = (const float*)d_in[11];
    const float* bwd_b1  = (const float*)d_in[12];
    const float* bwd_w2  = (const float*)d_in[13];
    const float* bwd_b2  = (const float*)d_in[14];
    const float* bwd_g   = (const float*)d_in[15];
    const float* bwd_be  = (const float*)d_in[16];
    float* out = (float*)d_out;

    static int smem_set = 0;
    if (!smem_set) {
        cudaFuncSetAttribute(gemm_kernel<0>, cudaFuncAttributeMaxDynamicSharedMemorySize, SMEM_BYTES);
        cudaFuncSetAttribute(gemm_kernel<1>, cudaFuncAttributeMaxDynamicSharedMemorySize, SMEM_BYTES);
        smem_set = 1;
    }

    prep_kernel<<<dim3(128, 12), 256>>>(fwd_w1, fwd_w2, bwd_w1, bwd_w2);

    dim3 ggrid(4, 256);   // N tiles x M tiles (both halves)

    for (int l = 0; l < 3; l++) {
        const float* pf = fwd_pad + (size_t)l * WW * DD;
        const float* pb = bwd_pad + (size_t)l * WW * DD;
        long long obase = (long long)l * NTOK * 1024;
        int use_x0 = (l == 0) ? 1 : 0;
        const float* prev = out + (size_t)(l > 0 ? (l - 1) : 0) * NTOK * 1024;

        winln_kernel<<<(2 * NTOK) / 8, 256>>>(x, prev, pf, pb,
                                              fwd_w + l * (WW + 1), bwd_w + l * (WW + 1),
                                              fwd_g + l * DD, fwd_be + l * DD,
                                              bwd_g + l * DD, bwd_be + l * DD,
                                              use_x0);
        gemm_kernel<0><<<ggrid, 256, SMEM_BYTES>>>(l * 4 + 0, l * 4 + 2,
                                                   fwd_b1 + l * DD, bwd_b1 + l * DD,
                                                   nullptr, 0);
        gemm_kernel<1><<<ggrid, 256, SMEM_BYTES>>>(l * 4 + 1, l * 4 + 3,
                                                   fwd_b2 + l * DD, bwd_b2 + l * DD,
                                                   out, obase);
    }
}